// round 8
// baseline (speedup 1.0000x reference)
#include <cuda_runtime.h>
#include <cstdint>

// Elman RNN split:
//   A) u[n,t,:] = x[n,t,:] @ W_ih^T + b_ih + b_hh   (parallel, streaming)
//   B) h_{t+1}  = tanh(u_t + h_t @ W_hh^T)          (serial, warp-per-sample)
// N=2048, T=512, I=32, H=64, O=1.
// B: 2048 one-warp blocks, lane l owns units (2l,2l+1), W_hh in 128 regs,
//    forced <=146 regs -> 14 blocks/SM -> single wave. h double-buffered in
//    smem; u prefetched 2 steps ahead; 2 fma.f32x2 chains (RAW spacing = 4cy).

#define TT 512
#define NN 2048

typedef unsigned long long ull;

__device__ float g_u[(size_t)NN * TT * 64];   // 268 MB scratch

__device__ __forceinline__ float tanh_acc(float s) {
    float e = __expf(2.0f * s);
    return 1.0f - __fdividef(2.0f, e + 1.0f);
}

// ---------------- Kernel A: streaming precompute of u ----------------
// grid = 2048 (block = sample), block = 128 threads = 4 warps.
// Warp w handles rows t in [128w, 128w+128). Lane l owns units (2l, 2l+1).
// x row staged in smem (double-buffered), read back as LDS.128 broadcast.
__global__ void __launch_bounds__(128) precompute_u_kernel(
    const float* __restrict__ x,      // [N, T, I]
    const float* __restrict__ W_ih,   // [H, I]
    const float* __restrict__ b_ih,   // [H]
    const float* __restrict__ b_hh)   // [H]
{
    __shared__ __align__(16) float xs[4][2][32];

    const int w  = threadIdx.x >> 5;
    const int l  = threadIdx.x & 31;
    const int n  = blockIdx.x;
    const int u0 = 2 * l;
    const int u1 = u0 + 1;

    // W_ih rows for this lane's 2 units: 32 ull = 64 regs
    ull W0[16], W1[16];
    {
        const ull* q0 = reinterpret_cast<const ull*>(W_ih + u0 * 32);
        const ull* q1 = reinterpret_cast<const ull*>(W_ih + u1 * 32);
        #pragma unroll
        for (int k = 0; k < 16; k++) { W0[k] = __ldg(q0 + k); W1[k] = __ldg(q1 + k); }
    }
    const float bias0 = __ldg(b_ih + u0) + __ldg(b_hh + u0);
    const float bias1 = __ldg(b_ih + u1) + __ldg(b_hh + u1);

    const int t0 = w * 128;
    const float* xb = x + (size_t)n * TT * 32;
    float* ub = g_u + (size_t)n * TT * 64;

    // stage first row
    xs[w][0][l] = __ldg(xb + t0 * 32 + l);
    __syncwarp();

    int p = 0;
    #pragma unroll 2
    for (int i = 0; i < 128; i++) {
        const int t = t0 + i;

        // prefetch next row (coalesced 128B per warp)
        const float xn = (i + 1 < 128) ? __ldg(xb + (t + 1) * 32 + l) : 0.0f;

        const ulonglong2* vp = reinterpret_cast<const ulonglong2*>(&xs[w][p][0]);

        // 2 chains (one per unit), depth 16, alternating issue -> spacing 4cy
        ull a0 = 0ull, a1 = 0ull;
        #pragma unroll
        for (int g = 0; g < 8; g++) {
            const ulonglong2 v = vp[g];
            asm("fma.rn.f32x2 %0, %1, %2, %0;" : "+l"(a0) : "l"(v.x), "l"(W0[2 * g]));
            asm("fma.rn.f32x2 %0, %1, %2, %0;" : "+l"(a1) : "l"(v.x), "l"(W1[2 * g]));
            asm("fma.rn.f32x2 %0, %1, %2, %0;" : "+l"(a0) : "l"(v.y), "l"(W0[2 * g + 1]));
            asm("fma.rn.f32x2 %0, %1, %2, %0;" : "+l"(a1) : "l"(v.y), "l"(W1[2 * g + 1]));
        }
        float r0x, r0y, r1x, r1y;
        asm("mov.b64 {%0, %1}, %2;" : "=f"(r0x), "=f"(r0y) : "l"(a0));
        asm("mov.b64 {%0, %1}, %2;" : "=f"(r1x), "=f"(r1y) : "l"(a1));

        // coalesced 256B store of u row
        *reinterpret_cast<float2*>(ub + t * 64 + u0) =
            make_float2(bias0 + r0x + r0y, bias1 + r1x + r1y);

        // publish next row into the other parity; one syncwarp per row
        xs[w][p ^ 1][l] = xn;
        __syncwarp();
        p ^= 1;
    }
}

// ---------------- Kernel B: serial recurrence, warp-per-sample ----------------
__global__ void __launch_bounds__(32, 14) rnn_rec_kernel(
    const float* __restrict__ W_hh,   // [H, H]
    const float* __restrict__ fc_w,   // [1, H]
    const float* __restrict__ fc_b,   // [1]
    float* __restrict__ out)          // [N, 1]
{
    __shared__ __align__(16) float buf[2][64];   // double-buffered h

    const int l  = threadIdx.x;
    const int n  = blockIdx.x;
    const int u0 = 2 * l;
    const int u1 = u0 + 1;

    // W_hh rows for this lane's 2 units: 64 ull = 128 regs
    ull W0[32], W1[32];
    {
        const ull* p0 = reinterpret_cast<const ull*>(W_hh + u0 * 64);
        const ull* p1 = reinterpret_cast<const ull*>(W_hh + u1 * 64);
        #pragma unroll
        for (int k = 0; k < 32; k++) { W0[k] = __ldg(p0 + k); W1[k] = __ldg(p1 + k); }
    }

    // u stream: lane l reads float2 (units u0,u1); 256B coalesced per warp-step
    const float2* up = reinterpret_cast<const float2*>(g_u + (size_t)n * TT * 64) + l;

    // init h0 = ones; prefetch u_0, u_1
    *reinterpret_cast<float2*>(&buf[0][u0]) = make_float2(1.0f, 1.0f);
    float2 uc = __ldg(up);
    float2 un = __ldg(up + 32);
    __syncwarp();

    float h0 = 1.0f, h1 = 1.0f;
    int par = 0;

    for (int t = 0; t < TT; t++) {
        // prefetch u_{t+2}: consumed ~2 step-walls later (covers DRAM latency)
        const float2 u2 = (t + 2 < TT) ? __ldg(up + (t + 2) * 32)
                                       : make_float2(0.0f, 0.0f);

        const ulonglong2* vp = reinterpret_cast<const ulonglong2*>(&buf[par][0]);

        // 2 chains (one per unit), depth 32; u_t seeds the lo half
        float2 s0 = make_float2(uc.x, 0.0f);
        float2 s1 = make_float2(uc.y, 0.0f);
        ull a0 = *reinterpret_cast<ull*>(&s0);
        ull a1 = *reinterpret_cast<ull*>(&s1);

        #pragma unroll
        for (int g = 0; g < 16; g++) {
            const ulonglong2 v = vp[g];
            asm("fma.rn.f32x2 %0, %1, %2, %0;" : "+l"(a0) : "l"(v.x), "l"(W0[2 * g]));
            asm("fma.rn.f32x2 %0, %1, %2, %0;" : "+l"(a1) : "l"(v.x), "l"(W1[2 * g]));
            asm("fma.rn.f32x2 %0, %1, %2, %0;" : "+l"(a0) : "l"(v.y), "l"(W0[2 * g + 1]));
            asm("fma.rn.f32x2 %0, %1, %2, %0;" : "+l"(a1) : "l"(v.y), "l"(W1[2 * g + 1]));
        }

        float r0x, r0y, r1x, r1y;
        asm("mov.b64 {%0, %1}, %2;" : "=f"(r0x), "=f"(r0y) : "l"(a0));
        asm("mov.b64 {%0, %1}, %2;" : "=f"(r1x), "=f"(r1y) : "l"(a1));

        h0 = tanh_acc(r0x + r0y);
        h1 = tanh_acc(r1x + r1y);

        *reinterpret_cast<float2*>(&buf[par ^ 1][u0]) = make_float2(h0, h1);
        __syncwarp();

        uc = un; un = u2;
        par ^= 1;
    }

    // output head: sigmoid(h . fc_w + fc_b)
    float p = h0 * fc_w[u0] + h1 * fc_w[u1];
    #pragma unroll
    for (int o = 16; o; o >>= 1) p += __shfl_xor_sync(0xffffffffu, p, o);
    if (l == 0)
        out[n] = __fdividef(1.0f, 1.0f + __expf(-(p + fc_b[0])));
}

extern "C" void kernel_launch(void* const* d_in, const int* in_sizes, int n_in,
                              void* d_out, int out_size) {
    const float* x    = (const float*)d_in[0];
    const float* W_ih = (const float*)d_in[1];
    const float* W_hh = (const float*)d_in[2];
    const float* b_ih = (const float*)d_in[3];
    const float* b_hh = (const float*)d_in[4];
    const float* fc_w = (const float*)d_in[5];
    const float* fc_b = (const float*)d_in[6];
    float* out = (float*)d_out;

    precompute_u_kernel<<<NN, 128>>>(x, W_ih, b_ih, b_hh);
    rnn_rec_kernel<<<NN, 32>>>(W_hh, fc_w, fc_b, out);
}

// round 9
// speedup vs baseline: 1.6026x; 1.6026x over previous
#include <cuda_runtime.h>
#include <cstdint>

// Elman RNN split:
//   A) u[n,t,:] = x[n,t,:] @ W_ih^T + b_ih + b_hh   (parallel, streaming, 4-row groups)
//   B) h_{t+1}  = tanh(u_t + h_t @ W_hh^T)          (serial, unit-per-thread)
// N=2048, T=512, I=32, H=64, O=1.
// B: 1024 blocks x 64 threads (2 warps) x 2 samples. Thread j owns unit j for
//    both samples -> W_hh row j = 64 regs only -> ~95 regs -> 10 blocks/SM
//    (5 warps/SMSP), single wave. One __syncthreads per step.

#define TT 512
#define NN 2048

typedef unsigned long long ull;

__device__ float g_u[(size_t)NN * TT * 64];   // 268 MB scratch

__device__ __forceinline__ float tanh_acc(float s) {
    float e = __expf(2.0f * s);
    return 1.0f - __fdividef(2.0f, e + 1.0f);
}

// ---------------- Kernel A: streaming precompute of u, 4-row groups ----------------
// grid = 2048 (block = sample), block = 128 = 4 warps. Warp w covers rows
// [128w, 128w+128) in groups of 4 rows. One LDG.128/lane loads a whole group.
__global__ void __launch_bounds__(128) precompute_u_kernel(
    const float* __restrict__ x,      // [N, T, I]
    const float* __restrict__ W_ih,   // [H, I]
    const float* __restrict__ b_ih,   // [H]
    const float* __restrict__ b_hh)   // [H]
{
    __shared__ __align__(16) float xs[4][2][128];   // [warp][parity][4 rows x 32]

    const int w  = threadIdx.x >> 5;
    const int l  = threadIdx.x & 31;
    const int n  = blockIdx.x;
    const int u0 = 2 * l;
    const int u1 = u0 + 1;

    // W_ih rows for this lane's 2 units: 32 ull = 64 regs
    ull W0[16], W1[16];
    {
        const ull* q0 = reinterpret_cast<const ull*>(W_ih + u0 * 32);
        const ull* q1 = reinterpret_cast<const ull*>(W_ih + u1 * 32);
        #pragma unroll
        for (int k = 0; k < 16; k++) { W0[k] = __ldg(q0 + k); W1[k] = __ldg(q1 + k); }
    }
    const float bias0 = __ldg(b_ih + u0) + __ldg(b_hh + u0);
    const float bias1 = __ldg(b_ih + u1) + __ldg(b_hh + u1);

    const int t0 = w * 128;
    const float* xb = x + (size_t)n * TT * 32;
    float* ub = g_u + (size_t)n * TT * 64;

    // stage group 0: 4 rows = 128 floats = 32 x float4 (one per lane)
    {
        const float4 v = __ldg(reinterpret_cast<const float4*>(xb + t0 * 32) + l);
        reinterpret_cast<float4*>(&xs[w][0][0])[l] = v;
    }
    __syncwarp();

    int p = 0;
    for (int g = 0; g < 32; g++) {
        // prefetch next group (coalesced 512B per warp)
        float4 vn = make_float4(0.f, 0.f, 0.f, 0.f);
        if (g + 1 < 32)
            vn = __ldg(reinterpret_cast<const float4*>(xb + (t0 + 4 * (g + 1)) * 32) + l);

        // compute 4 rows of this group
        #pragma unroll
        for (int r = 0; r < 4; r++) {
            const ulonglong2* vp =
                reinterpret_cast<const ulonglong2*>(&xs[w][p][r * 32]);
            ull a0 = 0ull, a1 = 0ull;
            #pragma unroll
            for (int q = 0; q < 8; q++) {
                const ulonglong2 v = vp[q];
                asm("fma.rn.f32x2 %0, %1, %2, %0;" : "+l"(a0) : "l"(v.x), "l"(W0[2 * q]));
                asm("fma.rn.f32x2 %0, %1, %2, %0;" : "+l"(a1) : "l"(v.x), "l"(W1[2 * q]));
                asm("fma.rn.f32x2 %0, %1, %2, %0;" : "+l"(a0) : "l"(v.y), "l"(W0[2 * q + 1]));
                asm("fma.rn.f32x2 %0, %1, %2, %0;" : "+l"(a1) : "l"(v.y), "l"(W1[2 * q + 1]));
            }
            float r0x, r0y, r1x, r1y;
            asm("mov.b64 {%0, %1}, %2;" : "=f"(r0x), "=f"(r0y) : "l"(a0));
            asm("mov.b64 {%0, %1}, %2;" : "=f"(r1x), "=f"(r1y) : "l"(a1));
            const int t = t0 + 4 * g + r;
            *reinterpret_cast<float2*>(ub + t * 64 + u0) =
                make_float2(bias0 + r0x + r0y, bias1 + r1x + r1y);
        }

        // publish next group into other parity; one syncwarp per group
        reinterpret_cast<float4*>(&xs[w][p ^ 1][0])[l] = vn;
        __syncwarp();
        p ^= 1;
    }
}

// ---------------- Kernel B: serial recurrence, unit-per-thread, 2 samples/block ----------------
__global__ void __launch_bounds__(64, 10) rnn_rec_kernel(
    const float* __restrict__ W_hh,   // [H, H]
    const float* __restrict__ fc_w,   // [1, H]
    const float* __restrict__ fc_b,   // [1]
    float* __restrict__ out)          // [N, 1]
{
    __shared__ __align__(16) float hb[2][2][64];   // [parity][sample][unit]
    __shared__ float wsum[2][2];                   // [warp][sample]

    const int j  = threadIdx.x;        // unit 0..63
    const int n0 = 2 * blockIdx.x;

    // W_hh row j: 32 ull = 64 regs
    ull W[32];
    {
        const ull* p = reinterpret_cast<const ull*>(W_hh + j * 64);
        #pragma unroll
        for (int k = 0; k < 32; k++) W[k] = __ldg(p + k);
    }

    // u streams: thread j reads u[n0+s][t][j]
    const float* up0 = g_u + (size_t)n0 * TT * 64 + j;
    const float* up1 = up0 + (size_t)TT * 64;

    // init h0 = ones; prefetch u_0, u_1 for both samples
    hb[0][0][j] = 1.0f;
    hb[0][1][j] = 1.0f;
    float uc0 = __ldg(up0),      uc1 = __ldg(up1);
    float un0 = __ldg(up0 + 64), un1 = __ldg(up1 + 64);
    __syncthreads();

    float h0 = 1.0f, h1 = 1.0f;
    int par = 0;

    for (int t = 0; t < TT; t++) {
        // prefetch u_{t+2} (distance-2, covers DRAM latency under ~2 step-walls)
        float u20 = 0.0f, u21 = 0.0f;
        if (t + 2 < TT) {
            u20 = __ldg(up0 + (t + 2) * 64);
            u21 = __ldg(up1 + (t + 2) * 64);
        }

        const ulonglong2* vp0 = reinterpret_cast<const ulonglong2*>(&hb[par][0][0]);
        const ulonglong2* vp1 = reinterpret_cast<const ulonglong2*>(&hb[par][1][0]);

        // one f32x2 chain per sample; alternating issue -> same-chain spacing 4cy
        float2 s0 = make_float2(uc0, 0.0f);
        float2 s1 = make_float2(uc1, 0.0f);
        ull a0 = *reinterpret_cast<ull*>(&s0);
        ull a1 = *reinterpret_cast<ull*>(&s1);

        #pragma unroll
        for (int g = 0; g < 16; g++) {
            const ulonglong2 v0 = vp0[g];
            const ulonglong2 v1 = vp1[g];
            asm("fma.rn.f32x2 %0, %1, %2, %0;" : "+l"(a0) : "l"(v0.x), "l"(W[2 * g]));
            asm("fma.rn.f32x2 %0, %1, %2, %0;" : "+l"(a1) : "l"(v1.x), "l"(W[2 * g]));
            asm("fma.rn.f32x2 %0, %1, %2, %0;" : "+l"(a0) : "l"(v0.y), "l"(W[2 * g + 1]));
            asm("fma.rn.f32x2 %0, %1, %2, %0;" : "+l"(a1) : "l"(v1.y), "l"(W[2 * g + 1]));
        }

        float r0x, r0y, r1x, r1y;
        asm("mov.b64 {%0, %1}, %2;" : "=f"(r0x), "=f"(r0y) : "l"(a0));
        asm("mov.b64 {%0, %1}, %2;" : "=f"(r1x), "=f"(r1y) : "l"(a1));

        h0 = tanh_acc(r0x + r0y);
        h1 = tanh_acc(r1x + r1y);

        hb[par ^ 1][0][j] = h0;
        hb[par ^ 1][1][j] = h1;
        __syncthreads();

        uc0 = un0; un0 = u20;
        uc1 = un1; un1 = u21;
        par ^= 1;
    }

    // ---- output heads: sigmoid(h . fc_w + fc_b) for both samples ----
    const float fw = fc_w[j];
    float p0 = h0 * fw;
    float p1 = h1 * fw;
    #pragma unroll
    for (int o = 16; o; o >>= 1) {
        p0 += __shfl_xor_sync(0xffffffffu, p0, o);
        p1 += __shfl_xor_sync(0xffffffffu, p1, o);
    }
    if ((j & 31) == 0) {
        wsum[j >> 5][0] = p0;
        wsum[j >> 5][1] = p1;
    }
    __syncthreads();
    if (j < 2) {
        const float s = wsum[0][j] + wsum[1][j] + fc_b[0];
        out[n0 + j] = __fdividef(1.0f, 1.0f + __expf(-s));
    }
}

extern "C" void kernel_launch(void* const* d_in, const int* in_sizes, int n_in,
                              void* d_out, int out_size) {
    const float* x    = (const float*)d_in[0];
    const float* W_ih = (const float*)d_in[1];
    const float* W_hh = (const float*)d_in[2];
    const float* b_ih = (const float*)d_in[3];
    const float* b_hh = (const float*)d_in[4];
    const float* fc_w = (const float*)d_in[5];
    const float* fc_b = (const float*)d_in[6];
    float* out = (float*)d_out;

    precompute_u_kernel<<<NN, 128>>>(x, W_ih, b_ih, b_hh);
    rnn_rec_kernel<<<NN / 2, 64>>>(W_hh, fc_w, fc_b, out);
}

// round 10
// speedup vs baseline: 1.6850x; 1.0515x over previous
#include <cuda_runtime.h>
#include <cstdint>

// Elman RNN split:
//   A) u[n,t,:] = x[n,t,:] @ W_ih^T + b_ih + b_hh   (parallel, streaming, 4-row groups)
//   B) h_{t+1}  = tanh(u_t + h_t @ W_hh^T)          (serial, unit-per-thread)
// N=2048, T=512, I=32, H=64, O=1.
// B: 1024 blocks x 64 threads (2 warps) x 2 samples. Thread j owns unit j for
//    both samples -> W_hh row j = 64 regs only -> ~95 regs -> 10 blocks/SM
//    (5 warps/SMSP), single wave. One __syncthreads per step.

#define TT 512
#define NN 2048

typedef unsigned long long ull;

__device__ float g_u[(size_t)NN * TT * 64];   // 268 MB scratch

__device__ __forceinline__ float tanh_acc(float s) {
    float e = __expf(2.0f * s);
    return 1.0f - __fdividef(2.0f, e + 1.0f);
}

// ---------------- Kernel A: streaming precompute of u, 4-row groups ----------------
// grid = 2048 (block = sample), block = 128 = 4 warps. Warp w covers rows
// [128w, 128w+128) in groups of 4 rows. One LDG.128/lane loads a whole group.
__global__ void __launch_bounds__(128) precompute_u_kernel(
    const float* __restrict__ x,      // [N, T, I]
    const float* __restrict__ W_ih,   // [H, I]
    const float* __restrict__ b_ih,   // [H]
    const float* __restrict__ b_hh)   // [H]
{
    __shared__ __align__(16) float xs[4][2][128];   // [warp][parity][4 rows x 32]

    const int w  = threadIdx.x >> 5;
    const int l  = threadIdx.x & 31;
    const int n  = blockIdx.x;
    const int u0 = 2 * l;
    const int u1 = u0 + 1;

    // W_ih rows for this lane's 2 units: 32 ull = 64 regs
    ull W0[16], W1[16];
    {
        const ull* q0 = reinterpret_cast<const ull*>(W_ih + u0 * 32);
        const ull* q1 = reinterpret_cast<const ull*>(W_ih + u1 * 32);
        #pragma unroll
        for (int k = 0; k < 16; k++) { W0[k] = __ldg(q0 + k); W1[k] = __ldg(q1 + k); }
    }
    const float bias0 = __ldg(b_ih + u0) + __ldg(b_hh + u0);
    const float bias1 = __ldg(b_ih + u1) + __ldg(b_hh + u1);

    const int t0 = w * 128;
    const float* xb = x + (size_t)n * TT * 32;
    float* ub = g_u + (size_t)n * TT * 64;

    // stage group 0: 4 rows = 128 floats = 32 x float4 (one per lane)
    {
        const float4 v = __ldg(reinterpret_cast<const float4*>(xb + t0 * 32) + l);
        reinterpret_cast<float4*>(&xs[w][0][0])[l] = v;
    }
    __syncwarp();

    int p = 0;
    for (int g = 0; g < 32; g++) {
        // prefetch next group (coalesced 512B per warp)
        float4 vn = make_float4(0.f, 0.f, 0.f, 0.f);
        if (g + 1 < 32)
            vn = __ldg(reinterpret_cast<const float4*>(xb + (t0 + 4 * (g + 1)) * 32) + l);

        // compute 4 rows of this group
        #pragma unroll
        for (int r = 0; r < 4; r++) {
            const ulonglong2* vp =
                reinterpret_cast<const ulonglong2*>(&xs[w][p][r * 32]);
            ull a0 = 0ull, a1 = 0ull;
            #pragma unroll
            for (int q = 0; q < 8; q++) {
                const ulonglong2 v = vp[q];
                asm("fma.rn.f32x2 %0, %1, %2, %0;" : "+l"(a0) : "l"(v.x), "l"(W0[2 * q]));
                asm("fma.rn.f32x2 %0, %1, %2, %0;" : "+l"(a1) : "l"(v.x), "l"(W1[2 * q]));
                asm("fma.rn.f32x2 %0, %1, %2, %0;" : "+l"(a0) : "l"(v.y), "l"(W0[2 * q + 1]));
                asm("fma.rn.f32x2 %0, %1, %2, %0;" : "+l"(a1) : "l"(v.y), "l"(W1[2 * q + 1]));
            }
            float r0x, r0y, r1x, r1y;
            asm("mov.b64 {%0, %1}, %2;" : "=f"(r0x), "=f"(r0y) : "l"(a0));
            asm("mov.b64 {%0, %1}, %2;" : "=f"(r1x), "=f"(r1y) : "l"(a1));
            const int t = t0 + 4 * g + r;
            *reinterpret_cast<float2*>(ub + t * 64 + u0) =
                make_float2(bias0 + r0x + r0y, bias1 + r1x + r1y);
        }

        // publish next group into other parity; one syncwarp per group
        reinterpret_cast<float4*>(&xs[w][p ^ 1][0])[l] = vn;
        __syncwarp();
        p ^= 1;
    }
}

// ---------------- Kernel B: serial recurrence, unit-per-thread, 2 samples/block ----------------
__global__ void __launch_bounds__(64, 10) rnn_rec_kernel(
    const float* __restrict__ W_hh,   // [H, H]
    const float* __restrict__ fc_w,   // [1, H]
    const float* __restrict__ fc_b,   // [1]
    float* __restrict__ out)          // [N, 1]
{
    __shared__ __align__(16) float hb[2][2][64];   // [parity][sample][unit]
    __shared__ float wsum[2][2];                   // [warp][sample]

    const int j  = threadIdx.x;        // unit 0..63
    const int n0 = 2 * blockIdx.x;

    // W_hh row j: 32 ull = 64 regs
    ull W[32];
    {
        const ull* p = reinterpret_cast<const ull*>(W_hh + j * 64);
        #pragma unroll
        for (int k = 0; k < 32; k++) W[k] = __ldg(p + k);
    }

    // u streams: thread j reads u[n0+s][t][j]
    const float* up0 = g_u + (size_t)n0 * TT * 64 + j;
    const float* up1 = up0 + (size_t)TT * 64;

    // init h0 = ones; prefetch u_0, u_1 for both samples
    hb[0][0][j] = 1.0f;
    hb[0][1][j] = 1.0f;
    float uc0 = __ldg(up0),      uc1 = __ldg(up1);
    float un0 = __ldg(up0 + 64), un1 = __ldg(up1 + 64);
    __syncthreads();

    float h0 = 1.0f, h1 = 1.0f;
    int par = 0;

    for (int t = 0; t < TT; t++) {
        // prefetch u_{t+2} (distance-2, covers DRAM latency under ~2 step-walls)
        float u20 = 0.0f, u21 = 0.0f;
        if (t + 2 < TT) {
            u20 = __ldg(up0 + (t + 2) * 64);
            u21 = __ldg(up1 + (t + 2) * 64);
        }

        const ulonglong2* vp0 = reinterpret_cast<const ulonglong2*>(&hb[par][0][0]);
        const ulonglong2* vp1 = reinterpret_cast<const ulonglong2*>(&hb[par][1][0]);

        // one f32x2 chain per sample; alternating issue -> same-chain spacing 4cy
        float2 s0 = make_float2(uc0, 0.0f);
        float2 s1 = make_float2(uc1, 0.0f);
        ull a0 = *reinterpret_cast<ull*>(&s0);
        ull a1 = *reinterpret_cast<ull*>(&s1);

        #pragma unroll
        for (int g = 0; g < 16; g++) {
            const ulonglong2 v0 = vp0[g];
            const ulonglong2 v1 = vp1[g];
            asm("fma.rn.f32x2 %0, %1, %2, %0;" : "+l"(a0) : "l"(v0.x), "l"(W[2 * g]));
            asm("fma.rn.f32x2 %0, %1, %2, %0;" : "+l"(a1) : "l"(v1.x), "l"(W[2 * g]));
            asm("fma.rn.f32x2 %0, %1, %2, %0;" : "+l"(a0) : "l"(v0.y), "l"(W[2 * g + 1]));
            asm("fma.rn.f32x2 %0, %1, %2, %0;" : "+l"(a1) : "l"(v1.y), "l"(W[2 * g + 1]));
        }

        float r0x, r0y, r1x, r1y;
        asm("mov.b64 {%0, %1}, %2;" : "=f"(r0x), "=f"(r0y) : "l"(a0));
        asm("mov.b64 {%0, %1}, %2;" : "=f"(r1x), "=f"(r1y) : "l"(a1));

        h0 = tanh_acc(r0x + r0y);
        h1 = tanh_acc(r1x + r1y);

        hb[par ^ 1][0][j] = h0;
        hb[par ^ 1][1][j] = h1;
        __syncthreads();

        uc0 = un0; un0 = u20;
        uc1 = un1; un1 = u21;
        par ^= 1;
    }

    // ---- output heads: sigmoid(h . fc_w + fc_b) for both samples ----
    const float fw = fc_w[j];
    float p0 = h0 * fw;
    float p1 = h1 * fw;
    #pragma unroll
    for (int o = 16; o; o >>= 1) {
        p0 += __shfl_xor_sync(0xffffffffu, p0, o);
        p1 += __shfl_xor_sync(0xffffffffu, p1, o);
    }
    if ((j & 31) == 0) {
        wsum[j >> 5][0] = p0;
        wsum[j >> 5][1] = p1;
    }
    __syncthreads();
    if (j < 2) {
        const float s = wsum[0][j] + wsum[1][j] + fc_b[0];
        out[n0 + j] = __fdividef(1.0f, 1.0f + __expf(-s));
    }
}

extern "C" void kernel_launch(void* const* d_in, const int* in_sizes, int n_in,
                              void* d_out, int out_size) {
    const float* x    = (const float*)d_in[0];
    const float* W_ih = (const float*)d_in[1];
    const float* W_hh = (const float*)d_in[2];
    const float* b_ih = (const float*)d_in[3];
    const float* b_hh = (const float*)d_in[4];
    const float* fc_w = (const float*)d_in[5];
    const float* fc_b = (const float*)d_in[6];
    float* out = (float*)d_out;

    precompute_u_kernel<<<NN, 128>>>(x, W_ih, b_ih, b_hh);
    rnn_rec_kernel<<<NN / 2, 64>>>(W_hh, fc_w, fc_b, out);
}